// round 7
// baseline (speedup 1.0000x reference)
#include <cuda_runtime.h>
#include <cuda_fp16.h>
#include <cstdint>

#define DCH 64
#define MAXN 131072
#define MAXE (1 << 21)

// Scratch (allocation-free rule: __device__ globals)
__device__ __align__(16) __half g_bufA[(size_t)MAXN * DCH]; // fp16 messages (ping)
__device__ __align__(16) __half g_bufB[(size_t)MAXN * DCH]; // fp16 messages (pong)
__device__ float g_dis[MAXN];
__device__ int   g_degE[MAXN];
__device__ int   g_rowptr[MAXN + 1];
__device__ int   g_cursor[MAXN];
__device__ int   g_col[MAXE];
__device__ int   g_bsum[256];

// ---------------------------------------------------------------------------
// Degree / normalization + CSR build
// ---------------------------------------------------------------------------
__global__ void count_deg_kernel(const int* __restrict__ dst, int E) {
    int i = blockIdx.x * blockDim.x + threadIdx.x;
    if (i < E) atomicAdd(&g_degE[dst[i]], 1);
}
// per-1024-chunk sums for the scan; also computes dis = rsqrt(deg+1)
__global__ void scanA_kernel(int n) {
    __shared__ int sh[256];
    int base = blockIdx.x * 1024 + threadIdx.x * 4;
    int s = 0;
#pragma unroll
    for (int i = 0; i < 4; i++) {
        int idx = base + i;
        if (idx < n) {
            int d = g_degE[idx];
            s += d;
            g_dis[idx] = rsqrtf((float)(d + 1));
        }
    }
    sh[threadIdx.x] = s;
    __syncthreads();
    for (int off = 128; off; off >>= 1) {
        if (threadIdx.x < off) sh[threadIdx.x] += sh[threadIdx.x + off];
        __syncthreads();
    }
    if (threadIdx.x == 0) g_bsum[blockIdx.x] = sh[0];
}
__global__ void scanB_kernel(int nb, int n, int E) {
    if (threadIdx.x == 0 && blockIdx.x == 0) {
        int run = 0;
        for (int i = 0; i < nb; i++) { int v = g_bsum[i]; g_bsum[i] = run; run += v; }
        g_rowptr[n] = E;
    }
}
__global__ void scanC_kernel(int n) {
    __shared__ int sh[256];
    int base = blockIdx.x * 1024 + threadIdx.x * 4;
    int v[4]; int mysum = 0;
#pragma unroll
    for (int i = 0; i < 4; i++) {
        v[i] = (base + i < n) ? g_degE[base + i] : 0;
        mysum += v[i];
    }
    sh[threadIdx.x] = mysum;
    __syncthreads();
    for (int off = 1; off < 256; off <<= 1) {
        int t = (threadIdx.x >= off) ? sh[threadIdx.x - off] : 0;
        __syncthreads();
        sh[threadIdx.x] += t;
        __syncthreads();
    }
    int run = sh[threadIdx.x] - mysum + g_bsum[blockIdx.x];
#pragma unroll
    for (int i = 0; i < 4; i++) {
        if (base + i < n) {
            g_rowptr[base + i] = run;
            g_cursor[base + i] = run;
            run += v[i];
        }
    }
}
__global__ void fill_kernel(const int* __restrict__ src, const int* __restrict__ dst, int E) {
    int e = blockIdx.x * blockDim.x + threadIdx.x;
    if (e < E) {
        int pos = atomicAdd(&g_cursor[dst[e]], 1);
        g_col[pos] = src[e];
    }
}

// ---------------------------------------------------------------------------
// fp16 helpers
// ---------------------------------------------------------------------------
__device__ __forceinline__ void acc_h8(float* a, uint4 v) {
    __half2 h0 = *(__half2*)&v.x, h1 = *(__half2*)&v.y;
    __half2 h2 = *(__half2*)&v.z, h3 = *(__half2*)&v.w;
    float2 f0 = __half22float2(h0), f1 = __half22float2(h1);
    float2 f2 = __half22float2(h2), f3 = __half22float2(h3);
    a[0] += f0.x; a[1] += f0.y; a[2] += f1.x; a[3] += f1.y;
    a[4] += f2.x; a[5] += f2.y; a[6] += f3.x; a[7] += f3.y;
}

// Shuffle-shared CSR gather for one node. 8-lane group per node; lane owns
// channels [c*8, c*8+8). Lanes cooperatively read 8 col indices, broadcast
// via shfl (width 8) -> 8 independent row gathers in flight per round.
__device__ __forceinline__ void gather_node(float* a, const __half* __restrict__ buf,
                                            int r, int c, unsigned gmask) {
    const uint4* gb = (const uint4*)buf;
    acc_h8(a, gb[(size_t)r * 8 + c]);            // self-loop
    int e0 = __ldg(&g_rowptr[r]), e1 = __ldg(&g_rowptr[r + 1]);
    for (int e = e0; e < e1; e += 8) {
        int idx = e + c;
        int s = (idx < e1) ? __ldg(&g_col[idx]) : -1;
#pragma unroll
        for (int j = 0; j < 8; j++) {
            int sj = __shfl_sync(gmask, s, j, 8);
            if (sj >= 0) acc_h8(a, gb[(size_t)sj * 8 + c]);
        }
    }
}

// ---------------------------------------------------------------------------
// Layer-1 GEMM (dense input x): BM=128, 256 threads, thread = 8 rows x 4 cols.
//   bufA[r] = f16( dis[r] * (x[r] @ W) )
// ---------------------------------------------------------------------------
__global__ void __launch_bounds__(256) gemm1_kernel(
    const float* __restrict__ in, const float* __restrict__ W, int n)
{
    __shared__ float xs[128 * DCH];   // 32 KB
    __shared__ float Ws[DCH * DCH];   // 16 KB
    int tid = threadIdx.x;

#pragma unroll
    for (int i = 0; i < 4; i++)
        ((float4*)Ws)[tid + 256 * i] = ((const float4*)W)[tid + 256 * i];

    int base = blockIdx.x * 128;
    int cg = (tid & 15) * 4;
#pragma unroll
    for (int rep = 0; rep < 8; rep++) {
        int lr = (tid >> 4) + rep * 16;
        int r = base + lr;
        float4 v = make_float4(0.f, 0.f, 0.f, 0.f);
        if (r < n) v = *(const float4*)(in + (size_t)r * DCH + cg);
        *(float4*)(xs + lr * DCH + cg) = v;
    }
    __syncthreads();

    int rbase = (tid >> 4) * 8;
    float4 acc[8];
#pragma unroll
    for (int i = 0; i < 8; i++) acc[i] = make_float4(0.f, 0.f, 0.f, 0.f);

#pragma unroll 8
    for (int k = 0; k < DCH; k++) {
        float4 w = *(const float4*)(Ws + k * DCH + cg);
#pragma unroll
        for (int i = 0; i < 8; i++) {
            float xv = xs[(rbase + i) * DCH + k];
            acc[i].x = fmaf(xv, w.x, acc[i].x);
            acc[i].y = fmaf(xv, w.y, acc[i].y);
            acc[i].z = fmaf(xv, w.z, acc[i].z);
            acc[i].w = fmaf(xv, w.w, acc[i].w);
        }
    }

#pragma unroll
    for (int i = 0; i < 8; i++) {
        int r = base + rbase + i;
        if (r < n) {
            float dr = g_dis[r];
            __half2 h0 = __floats2half2_rn(dr * acc[i].x, dr * acc[i].y);
            __half2 h1 = __floats2half2_rn(dr * acc[i].z, dr * acc[i].w);
            *(uint2*)(g_bufA + (size_t)r * DCH + cg) =
                make_uint2(*(uint32_t*)&h0, *(uint32_t*)&h1);
        }
    }
}

// ---------------------------------------------------------------------------
// Fused middle layer: gather(src buf) -> relu(dis*sum + bprev) -> GEMM W -> dst buf
// 512 threads, 64 nodes/block, 8 threads per node (gather) == 8 cols/thread (gemm).
// src and dst MUST be different buffers (no grid sync inside a kernel).
// ---------------------------------------------------------------------------
__global__ void __launch_bounds__(512) fused_kernel(
    const __half* __restrict__ srcbuf, __half* __restrict__ dstbuf,
    const float* __restrict__ W, const float* __restrict__ bprev, int n)
{
    __shared__ float xs[64 * DCH];    // 16 KB
    __shared__ float Ws[DCH * DCH];   // 16 KB
    int tid = threadIdx.x;

    // stage W (4096 floats = 1024 float4)
    ((float4*)Ws)[tid]       = ((const float4*)W)[tid];
    ((float4*)Ws)[tid + 512] = ((const float4*)W)[tid + 512];

    int ln = tid >> 3;          // node within block
    int c  = tid & 7;           // channel group [c*8, c*8+8)
    int r  = blockIdx.x * 64 + ln;
    unsigned gmask = 0xFFu << (8u * ((tid >> 3) & 3u));

    float a[8] = {0, 0, 0, 0, 0, 0, 0, 0};
    float dr = 0.f;
    if (r < n) {
        gather_node(a, srcbuf, r, c, gmask);
        dr = g_dis[r];
        float4 b0 = *(const float4*)(bprev + c * 8);
        float4 b1 = *(const float4*)(bprev + c * 8 + 4);
        a[0] = fmaxf(fmaf(dr, a[0], b0.x), 0.f);
        a[1] = fmaxf(fmaf(dr, a[1], b0.y), 0.f);
        a[2] = fmaxf(fmaf(dr, a[2], b0.z), 0.f);
        a[3] = fmaxf(fmaf(dr, a[3], b0.w), 0.f);
        a[4] = fmaxf(fmaf(dr, a[4], b1.x), 0.f);
        a[5] = fmaxf(fmaf(dr, a[5], b1.y), 0.f);
        a[6] = fmaxf(fmaf(dr, a[6], b1.z), 0.f);
        a[7] = fmaxf(fmaf(dr, a[7], b1.w), 0.f);
    }
    *(float4*)(xs + ln * DCH + c * 8)     = make_float4(a[0], a[1], a[2], a[3]);
    *(float4*)(xs + ln * DCH + c * 8 + 4) = make_float4(a[4], a[5], a[6], a[7]);
    __syncthreads();

    // GEMM: thread computes row ln, cols [c*8, c*8+8)
    float acc[8] = {0, 0, 0, 0, 0, 0, 0, 0};
#pragma unroll 8
    for (int k = 0; k < DCH; k++) {
        float xv = xs[ln * DCH + k];
        float4 w0 = *(const float4*)(Ws + k * DCH + c * 8);
        float4 w1 = *(const float4*)(Ws + k * DCH + c * 8 + 4);
        acc[0] = fmaf(xv, w0.x, acc[0]); acc[1] = fmaf(xv, w0.y, acc[1]);
        acc[2] = fmaf(xv, w0.z, acc[2]); acc[3] = fmaf(xv, w0.w, acc[3]);
        acc[4] = fmaf(xv, w1.x, acc[4]); acc[5] = fmaf(xv, w1.y, acc[5]);
        acc[6] = fmaf(xv, w1.z, acc[6]); acc[7] = fmaf(xv, w1.w, acc[7]);
    }

    if (r < n) {
        __half2 h0 = __floats2half2_rn(dr * acc[0], dr * acc[1]);
        __half2 h1 = __floats2half2_rn(dr * acc[2], dr * acc[3]);
        __half2 h2 = __floats2half2_rn(dr * acc[4], dr * acc[5]);
        __half2 h3 = __floats2half2_rn(dr * acc[6], dr * acc[7]);
        uint4 o = make_uint4(*(uint32_t*)&h0, *(uint32_t*)&h1,
                             *(uint32_t*)&h2, *(uint32_t*)&h3);
        *(uint4*)(dstbuf + (size_t)r * DCH + c * 8) = o;
    }
}

// ---------------------------------------------------------------------------
// Final gather: out[r] = dis[r]*sum(srcbuf) + b3
// ---------------------------------------------------------------------------
__global__ void __launch_bounds__(256) final_gather_kernel(
    const __half* __restrict__ srcbuf,
    const float* __restrict__ b, float* __restrict__ out, int n)
{
    int t = blockIdx.x * blockDim.x + threadIdx.x;
    int r = t >> 3;
    if (r >= n) return;
    int c = t & 7;
    unsigned gmask = 0xFFu << (8u * ((threadIdx.x >> 3) & 3u));

    float a[8] = {0, 0, 0, 0, 0, 0, 0, 0};
    gather_node(a, srcbuf, r, c, gmask);

    float dr = g_dis[r];
    float4 b0 = *(const float4*)(b + c * 8);
    float4 b1 = *(const float4*)(b + c * 8 + 4);
    float4 o0, o1;
    o0.x = fmaf(dr, a[0], b0.x); o0.y = fmaf(dr, a[1], b0.y);
    o0.z = fmaf(dr, a[2], b0.z); o0.w = fmaf(dr, a[3], b0.w);
    o1.x = fmaf(dr, a[4], b1.x); o1.y = fmaf(dr, a[5], b1.y);
    o1.z = fmaf(dr, a[6], b1.z); o1.w = fmaf(dr, a[7], b1.w);
    *(float4*)(out + (size_t)r * DCH + c * 8)     = o0;
    *(float4*)(out + (size_t)r * DCH + c * 8 + 4) = o1;
}

// ---------------------------------------------------------------------------
extern "C" void kernel_launch(void* const* d_in, const int* in_sizes, int n_in,
                              void* d_out, int out_size)
{
    const float* x  = (const float*)d_in[0];
    const int*   ei = (const int*)d_in[1];
    const float* W1 = (const float*)d_in[2];
    const float* b1 = (const float*)d_in[3];
    const float* W2 = (const float*)d_in[4];
    const float* b2 = (const float*)d_in[5];
    const float* W3 = (const float*)d_in[6];
    const float* b3 = (const float*)d_in[7];
    float* out = (float*)d_out;

    int n = in_sizes[0] / DCH;
    int E = in_sizes[1] / 2;
    const int* src = ei;
    const int* dst = ei + E;

    int nb_e   = (E + 255) / 256;
    int nb_sc  = (n + 1023) / 1024;
    int nb_gm  = (n + 127) / 128;
    int nb_fu  = (n + 63) / 64;
    int nb_gat = (int)(((long long)n * 8 + 255) / 256);

    // device pointers to the two message buffers
    void* pA = nullptr; cudaGetSymbolAddress(&pA, g_bufA);
    void* pB = nullptr; cudaGetSymbolAddress(&pB, g_bufB);
    __half* bufA = (__half*)pA;
    __half* bufB = (__half*)pB;

    // normalization + CSR build (recomputed every call)
    void* degE_ptr = nullptr;
    cudaGetSymbolAddress(&degE_ptr, g_degE);
    cudaMemsetAsync(degE_ptr, 0, (size_t)n * sizeof(int));
    count_deg_kernel<<<nb_e, 256>>>(dst, E);
    scanA_kernel<<<nb_sc, 256>>>(n);           // also computes g_dis
    scanB_kernel<<<1, 32>>>(nb_sc, n, E);
    scanC_kernel<<<nb_sc, 256>>>(n);
    fill_kernel<<<nb_e, 256>>>(src, dst, E);

    // layer 1: dense GEMM -> bufA
    gemm1_kernel<<<nb_gm, 256>>>(x, W1, n);
    // layer 2: gather bufA + finalize(b1) + GEMM W2 -> bufB
    fused_kernel<<<nb_fu, 512>>>(bufA, bufB, W2, b1, n);
    // layer 3: gather bufB + finalize(b2) + GEMM W3 -> bufA
    fused_kernel<<<nb_fu, 512>>>(bufB, bufA, W3, b2, n);
    // output: gather bufA + bias b3
    final_gather_kernel<<<nb_gat, 256>>>(bufA, b3, out, n);
}

// round 9
// speedup vs baseline: 1.0444x; 1.0444x over previous
#include <cuda_runtime.h>
#include <cuda_fp16.h>
#include <cstdint>

#define DCH 64
#define MAXN 131072
#define MAXE (1 << 21)

// Scratch (allocation-free rule: __device__ globals)
__device__ __align__(16) __half g_bufA[(size_t)MAXN * DCH]; // fp16 messages (ping)
__device__ __align__(16) __half g_bufB[(size_t)MAXN * DCH]; // fp16 messages (pong)
__device__ float g_dis[MAXN];
__device__ int   g_degE[MAXN];
__device__ int   g_rowptr[MAXN + 1];
__device__ int   g_cursor[MAXN];
__device__ int   g_col[MAXE];
__device__ int   g_bsum[256];

// ---------------------------------------------------------------------------
// Degree / normalization + CSR build
// ---------------------------------------------------------------------------
__global__ void count_deg_kernel(const int* __restrict__ dst, int E) {
    int i = blockIdx.x * blockDim.x + threadIdx.x;
    if (i < E) atomicAdd(&g_degE[dst[i]], 1);
}
// per-1024-chunk sums for the scan; also computes dis = rsqrt(deg+1)
__global__ void scanA_kernel(int n) {
    __shared__ int sh[256];
    int base = blockIdx.x * 1024 + threadIdx.x * 4;
    int s = 0;
#pragma unroll
    for (int i = 0; i < 4; i++) {
        int idx = base + i;
        if (idx < n) {
            int d = g_degE[idx];
            s += d;
            g_dis[idx] = rsqrtf((float)(d + 1));
        }
    }
    sh[threadIdx.x] = s;
    __syncthreads();
    for (int off = 128; off; off >>= 1) {
        if (threadIdx.x < off) sh[threadIdx.x] += sh[threadIdx.x + off];
        __syncthreads();
    }
    if (threadIdx.x == 0) g_bsum[blockIdx.x] = sh[0];
}
__global__ void scanB_kernel(int nb, int n, int E) {
    if (threadIdx.x == 0 && blockIdx.x == 0) {
        int run = 0;
        for (int i = 0; i < nb; i++) { int v = g_bsum[i]; g_bsum[i] = run; run += v; }
        g_rowptr[n] = E;
    }
}
__global__ void scanC_kernel(int n) {
    __shared__ int sh[256];
    int base = blockIdx.x * 1024 + threadIdx.x * 4;
    int v[4]; int mysum = 0;
#pragma unroll
    for (int i = 0; i < 4; i++) {
        v[i] = (base + i < n) ? g_degE[base + i] : 0;
        mysum += v[i];
    }
    sh[threadIdx.x] = mysum;
    __syncthreads();
    for (int off = 1; off < 256; off <<= 1) {
        int t = (threadIdx.x >= off) ? sh[threadIdx.x - off] : 0;
        __syncthreads();
        sh[threadIdx.x] += t;
        __syncthreads();
    }
    int run = sh[threadIdx.x] - mysum + g_bsum[blockIdx.x];
#pragma unroll
    for (int i = 0; i < 4; i++) {
        if (base + i < n) {
            g_rowptr[base + i] = run;
            g_cursor[base + i] = run;
            run += v[i];
        }
    }
}
__global__ void fill_kernel(const int* __restrict__ src, const int* __restrict__ dst, int E) {
    int e = blockIdx.x * blockDim.x + threadIdx.x;
    if (e < E) {
        int pos = atomicAdd(&g_cursor[dst[e]], 1);
        g_col[pos] = src[e];
    }
}

// ---------------------------------------------------------------------------
// fp16 helpers
// ---------------------------------------------------------------------------
__device__ __forceinline__ void acc_h8(float* a, uint4 v) {
    __half2 h0 = *(__half2*)&v.x, h1 = *(__half2*)&v.y;
    __half2 h2 = *(__half2*)&v.z, h3 = *(__half2*)&v.w;
    float2 f0 = __half22float2(h0), f1 = __half22float2(h1);
    float2 f2 = __half22float2(h2), f3 = __half22float2(h3);
    a[0] += f0.x; a[1] += f0.y; a[2] += f1.x; a[3] += f1.y;
    a[4] += f2.x; a[5] += f2.y; a[6] += f3.x; a[7] += f3.y;
}

// Per-thread serial CSR gather (R5-proven shape): 8 threads per node, lane owns
// channels [c*8, c*8+8). Col reads are same-address within the group -> merged
// by the coalescer; row reads of a group are one contiguous 128B line.
__device__ __forceinline__ void gather_node(float* a, const __half* __restrict__ buf,
                                            int r, int c) {
    const uint4* gb = (const uint4*)buf;
    acc_h8(a, gb[(size_t)r * 8 + c]);            // self-loop
    int e0 = __ldg(&g_rowptr[r]), e1 = __ldg(&g_rowptr[r + 1]);
#pragma unroll 4
    for (int e = e0; e < e1; e++) {
        int s = __ldg(&g_col[e]);
        acc_h8(a, gb[(size_t)s * 8 + c]);
    }
}

// ---------------------------------------------------------------------------
// Layer-1 GEMM (dense input x): BM=128, 256 threads, thread = 8 rows x 4 cols.
//   bufA[r] = f16( dis[r] * (x[r] @ W) )
// ---------------------------------------------------------------------------
__global__ void __launch_bounds__(256) gemm1_kernel(
    const float* __restrict__ in, const float* __restrict__ W, int n)
{
    __shared__ float xs[128 * DCH];   // 32 KB
    __shared__ float Ws[DCH * DCH];   // 16 KB
    int tid = threadIdx.x;

#pragma unroll
    for (int i = 0; i < 4; i++)
        ((float4*)Ws)[tid + 256 * i] = ((const float4*)W)[tid + 256 * i];

    int base = blockIdx.x * 128;
    int cg = (tid & 15) * 4;
#pragma unroll
    for (int rep = 0; rep < 8; rep++) {
        int lr = (tid >> 4) + rep * 16;
        int r = base + lr;
        float4 v = make_float4(0.f, 0.f, 0.f, 0.f);
        if (r < n) v = *(const float4*)(in + (size_t)r * DCH + cg);
        *(float4*)(xs + lr * DCH + cg) = v;
    }
    __syncthreads();

    int rbase = (tid >> 4) * 8;
    float4 acc[8];
#pragma unroll
    for (int i = 0; i < 8; i++) acc[i] = make_float4(0.f, 0.f, 0.f, 0.f);

#pragma unroll 8
    for (int k = 0; k < DCH; k++) {
        float4 w = *(const float4*)(Ws + k * DCH + cg);
#pragma unroll
        for (int i = 0; i < 8; i++) {
            float xv = xs[(rbase + i) * DCH + k];
            acc[i].x = fmaf(xv, w.x, acc[i].x);
            acc[i].y = fmaf(xv, w.y, acc[i].y);
            acc[i].z = fmaf(xv, w.z, acc[i].z);
            acc[i].w = fmaf(xv, w.w, acc[i].w);
        }
    }

#pragma unroll
    for (int i = 0; i < 8; i++) {
        int r = base + rbase + i;
        if (r < n) {
            float dr = g_dis[r];
            __half2 h0 = __floats2half2_rn(dr * acc[i].x, dr * acc[i].y);
            __half2 h1 = __floats2half2_rn(dr * acc[i].z, dr * acc[i].w);
            *(uint2*)(g_bufA + (size_t)r * DCH + cg) =
                make_uint2(*(uint32_t*)&h0, *(uint32_t*)&h1);
        }
    }
}

// ---------------------------------------------------------------------------
// Fused middle layer (lean): gather(src) -> relu(dis*sum + bprev) -> GEMM -> dst
// 256 threads, 32 nodes/block, 8 threads/node; gather is the R5 serial style.
// ---------------------------------------------------------------------------
__global__ void __launch_bounds__(256) fused_kernel(
    const __half* __restrict__ srcbuf, __half* __restrict__ dstbuf,
    const float* __restrict__ W, const float* __restrict__ bprev, int n)
{
    __shared__ float xs[32 * DCH];    // 8 KB
    __shared__ float Ws[DCH * DCH];   // 16 KB
    int tid = threadIdx.x;

    // stage W (4096 floats = 1024 float4, 4 per thread)
#pragma unroll
    for (int i = 0; i < 4; i++)
        ((float4*)Ws)[tid + 256 * i] = ((const float4*)W)[tid + 256 * i];

    int ln = tid >> 3;          // node within block (0..31)
    int c  = tid & 7;           // channel group [c*8, c*8+8)
    int r  = blockIdx.x * 32 + ln;

    float a[8] = {0, 0, 0, 0, 0, 0, 0, 0};
    float dr = 0.f;
    if (r < n) {
        gather_node(a, srcbuf, r, c);
        dr = g_dis[r];
        float4 b0 = *(const float4*)(bprev + c * 8);
        float4 b1 = *(const float4*)(bprev + c * 8 + 4);
        a[0] = fmaxf(fmaf(dr, a[0], b0.x), 0.f);
        a[1] = fmaxf(fmaf(dr, a[1], b0.y), 0.f);
        a[2] = fmaxf(fmaf(dr, a[2], b0.z), 0.f);
        a[3] = fmaxf(fmaf(dr, a[3], b0.w), 0.f);
        a[4] = fmaxf(fmaf(dr, a[4], b1.x), 0.f);
        a[5] = fmaxf(fmaf(dr, a[5], b1.y), 0.f);
        a[6] = fmaxf(fmaf(dr, a[6], b1.z), 0.f);
        a[7] = fmaxf(fmaf(dr, a[7], b1.w), 0.f);
    }
    *(float4*)(xs + ln * DCH + c * 8)     = make_float4(a[0], a[1], a[2], a[3]);
    *(float4*)(xs + ln * DCH + c * 8 + 4) = make_float4(a[4], a[5], a[6], a[7]);
    __syncthreads();

    // GEMM: thread computes row ln, cols [c*8, c*8+8)
    float acc[8] = {0, 0, 0, 0, 0, 0, 0, 0};
#pragma unroll 8
    for (int k = 0; k < DCH; k++) {
        float xv = xs[ln * DCH + k];
        float4 w0 = *(const float4*)(Ws + k * DCH + c * 8);
        float4 w1 = *(const float4*)(Ws + k * DCH + c * 8 + 4);
        acc[0] = fmaf(xv, w0.x, acc[0]); acc[1] = fmaf(xv, w0.y, acc[1]);
        acc[2] = fmaf(xv, w0.z, acc[2]); acc[3] = fmaf(xv, w0.w, acc[3]);
        acc[4] = fmaf(xv, w1.x, acc[4]); acc[5] = fmaf(xv, w1.y, acc[5]);
        acc[6] = fmaf(xv, w1.z, acc[6]); acc[7] = fmaf(xv, w1.w, acc[7]);
    }

    if (r < n) {
        __half2 h0 = __floats2half2_rn(dr * acc[0], dr * acc[1]);
        __half2 h1 = __floats2half2_rn(dr * acc[2], dr * acc[3]);
        __half2 h2 = __floats2half2_rn(dr * acc[4], dr * acc[5]);
        __half2 h3 = __floats2half2_rn(dr * acc[6], dr * acc[7]);
        uint4 o = make_uint4(*(uint32_t*)&h0, *(uint32_t*)&h1,
                             *(uint32_t*)&h2, *(uint32_t*)&h3);
        *(uint4*)(dstbuf + (size_t)r * DCH + c * 8) = o;
    }
}

// ---------------------------------------------------------------------------
// Final gather: out[r] = dis[r]*sum(srcbuf) + b3
// ---------------------------------------------------------------------------
__global__ void __launch_bounds__(256) final_gather_kernel(
    const __half* __restrict__ srcbuf,
    const float* __restrict__ b, float* __restrict__ out, int n)
{
    int t = blockIdx.x * blockDim.x + threadIdx.x;
    int r = t >> 3;
    if (r >= n) return;
    int c = t & 7;

    float a[8] = {0, 0, 0, 0, 0, 0, 0, 0};
    gather_node(a, srcbuf, r, c);

    float dr = g_dis[r];
    float4 b0 = *(const float4*)(b + c * 8);
    float4 b1 = *(const float4*)(b + c * 8 + 4);
    float4 o0, o1;
    o0.x = fmaf(dr, a[0], b0.x); o0.y = fmaf(dr, a[1], b0.y);
    o0.z = fmaf(dr, a[2], b0.z); o0.w = fmaf(dr, a[3], b0.w);
    o1.x = fmaf(dr, a[4], b1.x); o1.y = fmaf(dr, a[5], b1.y);
    o1.z = fmaf(dr, a[6], b1.z); o1.w = fmaf(dr, a[7], b1.w);
    *(float4*)(out + (size_t)r * DCH + c * 8)     = o0;
    *(float4*)(out + (size_t)r * DCH + c * 8 + 4) = o1;
}

// ---------------------------------------------------------------------------
extern "C" void kernel_launch(void* const* d_in, const int* in_sizes, int n_in,
                              void* d_out, int out_size)
{
    const float* x  = (const float*)d_in[0];
    const int*   ei = (const int*)d_in[1];
    const float* W1 = (const float*)d_in[2];
    const float* b1 = (const float*)d_in[3];
    const float* W2 = (const float*)d_in[4];
    const float* b2 = (const float*)d_in[5];
    const float* W3 = (const float*)d_in[6];
    const float* b3 = (const float*)d_in[7];
    float* out = (float*)d_out;

    int n = in_sizes[0] / DCH;
    int E = in_sizes[1] / 2;
    const int* src = ei;
    const int* dst = ei + E;

    int nb_e   = (E + 255) / 256;
    int nb_sc  = (n + 1023) / 1024;
    int nb_gm  = (n + 127) / 128;
    int nb_fu  = (n + 31) / 32;
    int nb_gat = (int)(((long long)n * 8 + 255) / 256);

    // device pointers to the two message buffers
    void* pA = nullptr; cudaGetSymbolAddress(&pA, g_bufA);
    void* pB = nullptr; cudaGetSymbolAddress(&pB, g_bufB);
    __half* bufA = (__half*)pA;
    __half* bufB = (__half*)pB;

    // normalization + CSR build (recomputed every call)
    void* degE_ptr = nullptr;
    cudaGetSymbolAddress(&degE_ptr, g_degE);
    cudaMemsetAsync(degE_ptr, 0, (size_t)n * sizeof(int));
    count_deg_kernel<<<nb_e, 256>>>(dst, E);
    scanA_kernel<<<nb_sc, 256>>>(n);           // also computes g_dis
    scanB_kernel<<<1, 32>>>(nb_sc, n, E);
    scanC_kernel<<<nb_sc, 256>>>(n);
    fill_kernel<<<nb_e, 256>>>(src, dst, E);

    // layer 1: dense GEMM -> bufA
    gemm1_kernel<<<nb_gm, 256>>>(x, W1, n);
    // layer 2: gather bufA + finalize(b1) + GEMM W2 -> bufB
    fused_kernel<<<nb_fu, 256>>>(bufA, bufB, W2, b1, n);
    // layer 3: gather bufB + finalize(b2) + GEMM W3 -> bufA
    fused_kernel<<<nb_fu, 256>>>(bufB, bufA, W3, b2, n);
    // output: gather bufA + bias b3
    final_gather_kernel<<<nb_gat, 256>>>(bufA, b3, out, n);
}

// round 11
// speedup vs baseline: 1.9363x; 1.8539x over previous
#include <cuda_runtime.h>
#include <cuda_fp16.h>
#include <cstdint>

#define DCH 64
#define MAXN 131072
#define MAXE (1 << 21)

// Scratch (allocation-free rule: __device__ globals)
__device__ __align__(16) __half g_bufA[(size_t)MAXN * DCH]; // messages
__device__ __align__(16) __half g_bufB[(size_t)MAXN * DCH]; // finalized h
__device__ float g_dis[MAXN];
__device__ int   g_degE[MAXN];
__device__ int   g_rowptr[MAXN + 1];
__device__ int   g_cursor[MAXN];
__device__ int   g_col[MAXE];
__device__ int   g_bsum[256];

// ---------------------------------------------------------------------------
// Degree / normalization + CSR build
// ---------------------------------------------------------------------------
__global__ void count_deg_kernel(const int* __restrict__ dst, int E) {
    int i = blockIdx.x * blockDim.x + threadIdx.x;
    if (i < E) atomicAdd(&g_degE[dst[i]], 1);
}
// per-1024-chunk sums for the scan; also computes dis = rsqrt(deg+1)
__global__ void scanA_kernel(int n) {
    __shared__ int sh[256];
    int base = blockIdx.x * 1024 + threadIdx.x * 4;
    int s = 0;
#pragma unroll
    for (int i = 0; i < 4; i++) {
        int idx = base + i;
        if (idx < n) {
            int d = g_degE[idx];
            s += d;
            g_dis[idx] = rsqrtf((float)(d + 1));
        }
    }
    sh[threadIdx.x] = s;
    __syncthreads();
    for (int off = 128; off; off >>= 1) {
        if (threadIdx.x < off) sh[threadIdx.x] += sh[threadIdx.x + off];
        __syncthreads();
    }
    if (threadIdx.x == 0) g_bsum[blockIdx.x] = sh[0];
}
// warp-parallel exclusive scan of the <=256 block sums
__global__ void scanB_kernel(int nb, int n, int E) {
    int lid = threadIdx.x;  // 32 threads
    int carry = 0;
    for (int base = 0; base < nb; base += 32) {
        int i = base + lid;
        int v = (i < nb) ? g_bsum[i] : 0;
        // inclusive shfl scan
        int x = v;
#pragma unroll
        for (int off = 1; off < 32; off <<= 1) {
            int t = __shfl_up_sync(0xFFFFFFFF, x, off);
            if (lid >= off) x += t;
        }
        if (i < nb) g_bsum[i] = carry + x - v;  // exclusive
        carry += __shfl_sync(0xFFFFFFFF, x, 31);
    }
    if (lid == 0) g_rowptr[n] = E;
}
__global__ void scanC_kernel(int n) {
    __shared__ int sh[256];
    int base = blockIdx.x * 1024 + threadIdx.x * 4;
    int v[4]; int mysum = 0;
#pragma unroll
    for (int i = 0; i < 4; i++) {
        v[i] = (base + i < n) ? g_degE[base + i] : 0;
        mysum += v[i];
    }
    sh[threadIdx.x] = mysum;
    __syncthreads();
    for (int off = 1; off < 256; off <<= 1) {
        int t = (threadIdx.x >= off) ? sh[threadIdx.x - off] : 0;
        __syncthreads();
        sh[threadIdx.x] += t;
        __syncthreads();
    }
    int run = sh[threadIdx.x] - mysum + g_bsum[blockIdx.x];
#pragma unroll
    for (int i = 0; i < 4; i++) {
        if (base + i < n) {
            g_rowptr[base + i] = run;
            g_cursor[base + i] = run;
            run += v[i];
        }
    }
}
__global__ void fill_kernel(const int* __restrict__ src, const int* __restrict__ dst, int E) {
    int e = blockIdx.x * blockDim.x + threadIdx.x;
    if (e < E) {
        int pos = atomicAdd(&g_cursor[dst[e]], 1);
        g_col[pos] = src[e];
    }
}

// ---------------------------------------------------------------------------
// fp16 helpers
// ---------------------------------------------------------------------------
__device__ __forceinline__ void acc_h8(float* a, uint4 v) {
    __half2 h0 = *(__half2*)&v.x, h1 = *(__half2*)&v.y;
    __half2 h2 = *(__half2*)&v.z, h3 = *(__half2*)&v.w;
    float2 f0 = __half22float2(h0), f1 = __half22float2(h1);
    float2 f2 = __half22float2(h2), f3 = __half22float2(h3);
    a[0] += f0.x; a[1] += f0.y; a[2] += f1.x; a[3] += f1.y;
    a[4] += f2.x; a[5] += f2.y; a[6] += f3.x; a[7] += f3.y;
}

// Per-thread serial CSR gather (R5-proven shape): 8 threads per node, lane owns
// channels [c*8, c*8+8). Col reads are same-address within the group -> merged
// by the coalescer; row reads of a group are one contiguous 128B line.
__device__ __forceinline__ void gather_node(float* a, const __half* __restrict__ buf,
                                            int r, int c) {
    const uint4* gb = (const uint4*)buf;
    acc_h8(a, gb[(size_t)r * 8 + c]);            // self-loop
    int e0 = __ldg(&g_rowptr[r]), e1 = __ldg(&g_rowptr[r + 1]);
#pragma unroll 4
    for (int e = e0; e < e1; e++) {
        int s = __ldg(&g_col[e]);
        acc_h8(a, gb[(size_t)s * 8 + c]);
    }
}

// ---------------------------------------------------------------------------
// Layer-1 GEMM (dense fp32 input x): BM=128, 256 threads, 8 rows x 4 cols/thread.
//   bufA[r] = f16( dis[r] * (x[r] @ W) )
// ---------------------------------------------------------------------------
__global__ void __launch_bounds__(256) gemm1_kernel(
    const float* __restrict__ in, const float* __restrict__ W, int n)
{
    __shared__ float xs[128 * DCH];   // 32 KB
    __shared__ float Ws[DCH * DCH];   // 16 KB
    int tid = threadIdx.x;

#pragma unroll
    for (int i = 0; i < 4; i++)
        ((float4*)Ws)[tid + 256 * i] = ((const float4*)W)[tid + 256 * i];

    int base = blockIdx.x * 128;
    int cg = (tid & 15) * 4;
#pragma unroll
    for (int rep = 0; rep < 8; rep++) {
        int lr = (tid >> 4) + rep * 16;
        int r = base + lr;
        float4 v = make_float4(0.f, 0.f, 0.f, 0.f);
        if (r < n) v = *(const float4*)(in + (size_t)r * DCH + cg);
        *(float4*)(xs + lr * DCH + cg) = v;
    }
    __syncthreads();

    int rbase = (tid >> 4) * 8;
    float4 acc[8];
#pragma unroll
    for (int i = 0; i < 8; i++) acc[i] = make_float4(0.f, 0.f, 0.f, 0.f);

#pragma unroll 8
    for (int k = 0; k < DCH; k++) {
        float4 w = *(const float4*)(Ws + k * DCH + cg);
#pragma unroll
        for (int i = 0; i < 8; i++) {
            float xv = xs[(rbase + i) * DCH + k];
            acc[i].x = fmaf(xv, w.x, acc[i].x);
            acc[i].y = fmaf(xv, w.y, acc[i].y);
            acc[i].z = fmaf(xv, w.z, acc[i].z);
            acc[i].w = fmaf(xv, w.w, acc[i].w);
        }
    }

#pragma unroll
    for (int i = 0; i < 8; i++) {
        int r = base + rbase + i;
        if (r < n) {
            float dr = g_dis[r];
            __half2 h0 = __floats2half2_rn(dr * acc[i].x, dr * acc[i].y);
            __half2 h1 = __floats2half2_rn(dr * acc[i].z, dr * acc[i].w);
            *(uint2*)(g_bufA + (size_t)r * DCH + cg) =
                make_uint2(*(uint32_t*)&h0, *(uint32_t*)&h1);
        }
    }
}

// ---------------------------------------------------------------------------
// Middle GEMM (fp16 finalized input h): same tiling, converts h->fp32 in smem.
//   dstbuf[r] = f16( dis[r] * (h[r] @ W) )
// ---------------------------------------------------------------------------
__global__ void __launch_bounds__(256) gemm_mid_kernel(
    const __half* __restrict__ h, __half* __restrict__ dstbuf,
    const float* __restrict__ W, int n)
{
    __shared__ float xs[128 * DCH];   // 32 KB
    __shared__ float Ws[DCH * DCH];   // 16 KB
    int tid = threadIdx.x;

#pragma unroll
    for (int i = 0; i < 4; i++)
        ((float4*)Ws)[tid + 256 * i] = ((const float4*)W)[tid + 256 * i];

    int base = blockIdx.x * 128;
    int cg = (tid & 15) * 4;
#pragma unroll
    for (int rep = 0; rep < 8; rep++) {
        int lr = (tid >> 4) + rep * 16;
        int r = base + lr;
        float4 v = make_float4(0.f, 0.f, 0.f, 0.f);
        if (r < n) {
            uint2 u = *(const uint2*)(h + (size_t)r * DCH + cg);
            float2 f0 = __half22float2(*(__half2*)&u.x);
            float2 f1 = __half22float2(*(__half2*)&u.y);
            v = make_float4(f0.x, f0.y, f1.x, f1.y);
        }
        *(float4*)(xs + lr * DCH + cg) = v;
    }
    __syncthreads();

    int rbase = (tid >> 4) * 8;
    float4 acc[8];
#pragma unroll
    for (int i = 0; i < 8; i++) acc[i] = make_float4(0.f, 0.f, 0.f, 0.f);

#pragma unroll 8
    for (int k = 0; k < DCH; k++) {
        float4 w = *(const float4*)(Ws + k * DCH + cg);
#pragma unroll
        for (int i = 0; i < 8; i++) {
            float xv = xs[(rbase + i) * DCH + k];
            acc[i].x = fmaf(xv, w.x, acc[i].x);
            acc[i].y = fmaf(xv, w.y, acc[i].y);
            acc[i].z = fmaf(xv, w.z, acc[i].z);
            acc[i].w = fmaf(xv, w.w, acc[i].w);
        }
    }

#pragma unroll
    for (int i = 0; i < 8; i++) {
        int r = base + rbase + i;
        if (r < n) {
            float dr = g_dis[r];
            __half2 h0 = __floats2half2_rn(dr * acc[i].x, dr * acc[i].y);
            __half2 h1 = __floats2half2_rn(dr * acc[i].z, dr * acc[i].w);
            *(uint2*)(dstbuf + (size_t)r * DCH + cg) =
                make_uint2(*(uint32_t*)&h0, *(uint32_t*)&h1);
        }
    }
}

// ---------------------------------------------------------------------------
// Middle gather: h[r] = f16( relu(dis[r]*sum(msg) + b) )   (barrier-free)
// ---------------------------------------------------------------------------
__global__ void __launch_bounds__(256) gather_mid_kernel(
    const __half* __restrict__ srcbuf, __half* __restrict__ dsth,
    const float* __restrict__ b, int n)
{
    int t = blockIdx.x * blockDim.x + threadIdx.x;
    int r = t >> 3;
    if (r >= n) return;
    int c = t & 7;

    float a[8] = {0, 0, 0, 0, 0, 0, 0, 0};
    gather_node(a, srcbuf, r, c);

    float dr = g_dis[r];
    float4 b0 = *(const float4*)(b + c * 8);
    float4 b1 = *(const float4*)(b + c * 8 + 4);
    float h0 = fmaxf(fmaf(dr, a[0], b0.x), 0.f);
    float h1 = fmaxf(fmaf(dr, a[1], b0.y), 0.f);
    float h2 = fmaxf(fmaf(dr, a[2], b0.z), 0.f);
    float h3 = fmaxf(fmaf(dr, a[3], b0.w), 0.f);
    float h4 = fmaxf(fmaf(dr, a[4], b1.x), 0.f);
    float h5 = fmaxf(fmaf(dr, a[5], b1.y), 0.f);
    float h6 = fmaxf(fmaf(dr, a[6], b1.z), 0.f);
    float h7 = fmaxf(fmaf(dr, a[7], b1.w), 0.f);
    __half2 p0 = __floats2half2_rn(h0, h1);
    __half2 p1 = __floats2half2_rn(h2, h3);
    __half2 p2 = __floats2half2_rn(h4, h5);
    __half2 p3 = __floats2half2_rn(h6, h7);
    uint4 o = make_uint4(*(uint32_t*)&p0, *(uint32_t*)&p1,
                         *(uint32_t*)&p2, *(uint32_t*)&p3);
    *(uint4*)(dsth + (size_t)r * DCH + c * 8) = o;
}

// ---------------------------------------------------------------------------
// Final gather: out[r] = dis[r]*sum(srcbuf) + b3   (fp32 output)
// ---------------------------------------------------------------------------
__global__ void __launch_bounds__(256) final_gather_kernel(
    const __half* __restrict__ srcbuf,
    const float* __restrict__ b, float* __restrict__ out, int n)
{
    int t = blockIdx.x * blockDim.x + threadIdx.x;
    int r = t >> 3;
    if (r >= n) return;
    int c = t & 7;

    float a[8] = {0, 0, 0, 0, 0, 0, 0, 0};
    gather_node(a, srcbuf, r, c);

    float dr = g_dis[r];
    float4 b0 = *(const float4*)(b + c * 8);
    float4 b1 = *(const float4*)(b + c * 8 + 4);
    float4 o0, o1;
    o0.x = fmaf(dr, a[0], b0.x); o0.y = fmaf(dr, a[1], b0.y);
    o0.z = fmaf(dr, a[2], b0.z); o0.w = fmaf(dr, a[3], b0.w);
    o1.x = fmaf(dr, a[4], b1.x); o1.y = fmaf(dr, a[5], b1.y);
    o1.z = fmaf(dr, a[6], b1.z); o1.w = fmaf(dr, a[7], b1.w);
    *(float4*)(out + (size_t)r * DCH + c * 8)     = o0;
    *(float4*)(out + (size_t)r * DCH + c * 8 + 4) = o1;
}

// ---------------------------------------------------------------------------
extern "C" void kernel_launch(void* const* d_in, const int* in_sizes, int n_in,
                              void* d_out, int out_size)
{
    const float* x  = (const float*)d_in[0];
    const int*   ei = (const int*)d_in[1];
    const float* W1 = (const float*)d_in[2];
    const float* b1 = (const float*)d_in[3];
    const float* W2 = (const float*)d_in[4];
    const float* b2 = (const float*)d_in[5];
    const float* W3 = (const float*)d_in[6];
    const float* b3 = (const float*)d_in[7];
    float* out = (float*)d_out;

    int n = in_sizes[0] / DCH;
    int E = in_sizes[1] / 2;
    const int* src = ei;
    const int* dst = ei + E;

    int nb_e   = (E + 255) / 256;
    int nb_sc  = (n + 1023) / 1024;
    int nb_gm  = (n + 127) / 128;
    int nb_gat = (int)(((long long)n * 8 + 255) / 256);

    // device pointers to the two buffers
    void* pA = nullptr; cudaGetSymbolAddress(&pA, g_bufA);
    void* pB = nullptr; cudaGetSymbolAddress(&pB, g_bufB);
    __half* bufA = (__half*)pA;
    __half* bufB = (__half*)pB;

    // normalization + CSR build (recomputed every call)
    void* degE_ptr = nullptr;
    cudaGetSymbolAddress(&degE_ptr, g_degE);
    cudaMemsetAsync(degE_ptr, 0, (size_t)n * sizeof(int));
    count_deg_kernel<<<nb_e, 256>>>(dst, E);
    scanA_kernel<<<nb_sc, 256>>>(n);           // also computes g_dis
    scanB_kernel<<<1, 32>>>(nb_sc, n, E);
    scanC_kernel<<<nb_sc, 256>>>(n);
    fill_kernel<<<nb_e, 256>>>(src, dst, E);

    // layer 1: dense GEMM -> msg in bufA
    gemm1_kernel<<<nb_gm, 256>>>(x, W1, n);
    // gather1 + finalize(b1): h1 fp16 -> bufB
    gather_mid_kernel<<<nb_gat, 256>>>(bufA, bufB, b1, n);
    // layer 2 GEMM: h1 @ W2 -> msg in bufA
    gemm_mid_kernel<<<nb_gm, 256>>>(bufB, bufA, W2, n);
    // gather2 + finalize(b2): h2 fp16 -> bufB
    gather_mid_kernel<<<nb_gat, 256>>>(bufA, bufB, b2, n);
    // layer 3 GEMM: h2 @ W3 -> msg in bufA
    gemm_mid_kernel<<<nb_gm, 256>>>(bufB, bufA, W3, n);
    // output: gather msg + bias b3 (fp32)
    final_gather_kernel<<<nb_gat, 256>>>(bufA, b3, out, n);
}